// round 3
// baseline (speedup 1.0000x reference)
#include <cuda_runtime.h>
#include <cstdint>
#include <cstddef>

#define NN 8192
#define RWD 10
#define HD1 100
#define HD2 100
#define NB_SEG 256

typedef unsigned long long u64;

// ---------------- scratch (static device arrays; no allocation) ----------------
__device__ float g_hopX[3 * NN * RWD];      // hopX[k][n][d]
__device__ float g_nodeout[NN * HD2];       // per-node summed MLP output

// ---------------- helpers ----------------
__device__ __forceinline__ void fma2(u64 &acc, u64 a, u64 b) {
    asm("fma.rn.f32x2 %0, %1, %2, %0;" : "+l"(acc) : "l"(a), "l"(b));
}
__device__ __forceinline__ u64 pack2(float x, float y) {
    u64 r; asm("mov.b64 %0, {%1, %2};" : "=l"(r) : "f"(x), "f"(y)); return r;
}
__device__ __forceinline__ float2 unpack2(u64 v) {
    float2 r; asm("mov.b64 {%0, %1}, %2;" : "=f"(r.x), "=f"(r.y) : "l"(v)); return r;
}
__device__ __forceinline__ void cp_async16(uint32_t dst, const void* src) {
    asm volatile("cp.async.cg.shared.global [%0], [%1], 16;" :: "r"(dst), "l"(src));
}
__device__ __forceinline__ void cp_commit() { asm volatile("cp.async.commit_group;"); }
template<int N> __device__ __forceinline__ void cp_wait() {
    asm volatile("cp.async.wait_group %0;" :: "n"(N));
}

// =====================================================================
// Kernel A: hopX[k] = hop_k (8192x8192) @ X (8192x10)
// Block: 256 thr, 32 rows, m-chunks of 128. Lanes = rows; warp w owns
// mm slice [4w*4, 4w*4+16). Hop tile XOR-swizzled float4 SMEM; X broadcast.
// =====================================================================
#define MC 128
#define RB 32
#define NITER (NN / MC)   // 64

// smem layout (bytes): hs[2] @0,16384 (each 32x32 float4); xs[2] @32768,+5120; red @43008 (10240)
#define SMEM_A_BYTES 53248

extern "C" __global__ void __launch_bounds__(256)
hop_gemv_kernel(const float* __restrict__ hop0, const float* __restrict__ hop1,
                const float* __restrict__ hop2, const float* __restrict__ X)
{
    extern __shared__ char smem[];
    float4* hsb[2] = { (float4*)smem, (float4*)(smem + 16384) };
    float*  xsb[2] = { (float*)(smem + 32768), (float*)(smem + 32768 + 5120) };
    float*  red    = (float*)(smem + 43008);

    const int b    = blockIdx.x;
    const int k    = b >> 8;                 // 0..2
    const int row0 = (b & 255) * RB;
    const float* hop = (k == 0) ? hop0 : (k == 1) ? hop1 : hop2;

    const int t = threadIdx.x;
    const int w = t >> 5, l = t & 31;

    auto stage = [&](int buf, int it) {
        const int m0 = it * MC;
        const float* src = hop + (size_t)row0 * NN + m0;
        #pragma unroll
        for (int i = 0; i < 4; i++) {
            int f = i * 256 + t;
            int row = f >> 5, c4 = f & 31;
            uint32_t dst = (uint32_t)__cvta_generic_to_shared(
                &hsb[buf][row * 32 + (c4 ^ (row & 7))]);
            cp_async16(dst, src + (size_t)row * NN + c4 * 4);
        }
        // X chunk: 128 rows x 10 floats = 5120B contiguous = 320 float4
        const float4* xsrc = (const float4*)(X + (size_t)m0 * RWD);
        uint32_t xdst = (uint32_t)__cvta_generic_to_shared(xsb[buf]);
        cp_async16(xdst + t * 16, xsrc + t);
        if (t < 64) cp_async16(xdst + (256 + t) * 16, xsrc + 256 + t);
        cp_commit();
    };

    u64 acc[5] = {0, 0, 0, 0, 0};

    stage(0, 0);
    #pragma unroll 1
    for (int it = 0; it < NITER; it++) {
        if (it + 1 < NITER) { stage((it + 1) & 1, it + 1); cp_wait<1>(); }
        else                { cp_wait<0>(); }
        __syncthreads();

        const float4* hb = hsb[it & 1];
        const u64*    xb = (const u64*)xsb[it & 1];
        #pragma unroll
        for (int q = 0; q < 4; q++) {
            const int c4 = w * 4 + q;                       // float4 column
            float4 h4 = hb[l * 32 + (c4 ^ (l & 7))];        // rows = lanes, conflict-free
            const u64* xp = xb + c4 * 20;                   // mm=c4*4+j, 5 u64 per mm
            float hv[4] = {h4.x, h4.y, h4.z, h4.w};
            #pragma unroll
            for (int j = 0; j < 4; j++) {
                u64 A = pack2(hv[j], hv[j]);
                #pragma unroll
                for (int p = 0; p < 5; p++)
                    fma2(acc[p], A, xp[j * 5 + p]);
            }
        }
        __syncthreads();
    }

    // cross-warp reduction (each warp covered a different mm slice)
    #pragma unroll
    for (int p = 0; p < 5; p++) {
        float2 v = unpack2(acc[p]);
        red[(w * 32 + l) * 10 + 2 * p]     = v.x;
        red[(w * 32 + l) * 10 + 2 * p + 1] = v.y;
    }
    __syncthreads();
    // 320 output entries (32 rows x 10 d), 256 threads -> strided loop (was the
    // R2 bug: `if (t < 320)` left rows 25..31 unwritten)
    for (int f = t; f < RB * RWD; f += 256) {
        int row = f / RWD, d = f % RWD;
        float s = 0.f;
        #pragma unroll
        for (int ww = 0; ww < 8; ww++) s += red[(ww * 32 + row) * 10 + d];
        g_hopX[((size_t)k * NN + row0 + row) * RWD + d] = s;
    }
}

// =====================================================================
// Kernel B: per node n: sum_k [ relu(inp_k . W1_k + b1_k) . W2_k ] + sum_k b2_k
// Block = 256 thr, 32 nodes. All weights for current k in SMEM; W2 stored
// transposed [o][d] so both h and W2 reads vectorize along d (LDS.128).
// Register tile: 2 nodes x 7 outputs, FFMA2 along d-pairs.
// =====================================================================
// smem floats: w2t[112*100] + hsm[32*100] + w1t[100*12] + inp[320] + b1s[100] + b2s[100]
#define SMEM_B_BYTES ((112*100 + 32*100 + 100*12 + 320 + 100 + 100) * 4)

extern "C" __global__ void __launch_bounds__(256)
mlp_kernel(const float* __restrict__ X, const float* __restrict__ W1,
           const float* __restrict__ b1, const float* __restrict__ W2,
           const float* __restrict__ b2)
{
    extern __shared__ char smemb[];
    float* w2t = (float*)smemb;             // [112][100]  (rows 100..111 zero)
    float* hsm = w2t + 112 * 100;           // [32][100]
    float* w1t = hsm + 32 * 100;            // [100][12]
    float* inp = w1t + 100 * 12;            // [320]
    float* b1s = inp + 320;                 // [100]
    float* b2s = b1s + 100;                 // [100]

    const int t = threadIdx.x;
    const int node0 = blockIdx.x * 32;

    if (t < 100) b2s[t] = b2[t] + b2[100 + t] + b2[200 + t] + b2[300 + t];
    for (int f = t; f < 12 * 100; f += 256) w2t[100 * 100 + f] = 0.0f;

    const int r0 = t & 15;            // phase-2 node row base (lane stride 1 -> no bank conflicts)
    const int ob = (t >> 4) * 7;      // phase-2 output base (16 tiles x 7 = 112)
    u64 acc[2][7];
    #pragma unroll
    for (int g = 0; g < 2; g++)
        #pragma unroll
        for (int o = 0; o < 7; o++) acc[g][o] = 0ull;

    for (int k = 0; k < 4; k++) {
        __syncthreads();  // previous phase-2 finished before overwriting weights
        for (int f = t; f < 10000; f += 256) {
            int d = f / 100, o = f % 100;
            w2t[o * 100 + d] = W2[k * 10000 + f];     // transpose: [o][d]
        }
        for (int f = t; f < 1000; f += 256) {
            int r = f / 100, j = f % 100;
            w1t[j * 12 + r] = W1[k * 1000 + f];       // transpose: [j][r]
        }
        if (t < 100) b1s[t] = b1[k * 100 + t];
        const float* src = (k == 0) ? (X + (size_t)node0 * RWD)
                                    : (g_hopX + ((size_t)(k - 1) * NN + node0) * RWD);
        for (int f = t; f < 320; f += 256) inp[f] = src[f];
        __syncthreads();

        // phase 1: hsm[i][j] = relu(b1 + inp[i].W1[:,j])
        {
            const int i = t >> 3, jq = t & 7;
            float xr[10];
            #pragma unroll
            for (int r = 0; r < 10; r++) xr[r] = inp[i * 10 + r];
            #pragma unroll
            for (int jj = 0; jj < 13; jj++) {
                int j = jq * 13 + jj;
                if (j < 100) {
                    float s = b1s[j];
                    #pragma unroll
                    for (int r = 0; r < 10; r++) s = fmaf(xr[r], w1t[j * 12 + r], s);
                    hsm[i * 100 + j] = fmaxf(s, 0.0f);
                }
            }
        }
        __syncthreads();

        // phase 2: acc[g][oo] += hsm[row].w2t[o] over d (4 d's per iter, f32x2 pairs)
        #pragma unroll 5
        for (int d4 = 0; d4 < 25; d4++) {
            ulonglong2 h[2];
            #pragma unroll
            for (int g = 0; g < 2; g++)
                h[g] = *(const ulonglong2*)&hsm[(r0 + 16 * g) * 100 + d4 * 4];
            #pragma unroll
            for (int oo = 0; oo < 7; oo++) {
                ulonglong2 wv = *(const ulonglong2*)&w2t[(ob + oo) * 100 + d4 * 4];
                #pragma unroll
                for (int g = 0; g < 2; g++) {
                    fma2(acc[g][oo], h[g].x, wv.x);
                    fma2(acc[g][oo], h[g].y, wv.y);
                }
            }
        }
    }

    #pragma unroll
    for (int g = 0; g < 2; g++) {
        int n = node0 + r0 + 16 * g;
        #pragma unroll
        for (int oo = 0; oo < 7; oo++) {
            int o = ob + oo;
            if (o < 100) {
                float2 v = unpack2(acc[g][oo]);
                g_nodeout[(size_t)n * 100 + o] = v.x + v.y + b2s[o];
            }
        }
    }
}

// =====================================================================
// Kernel C: deterministic segment sum via binary search on sorted batch_idx
// =====================================================================
__device__ __forceinline__ int lbound(const int* a, int n, int v) {
    int lo = 0, hi = n;
    while (lo < hi) { int mid = (lo + hi) >> 1; if (a[mid] < v) lo = mid + 1; else hi = mid; }
    return lo;
}

extern "C" __global__ void segpool_kernel(const int* __restrict__ bidx,
                                          float* __restrict__ out)
{
    const int b = blockIdx.x;
    const int lo = lbound(bidx, NN, b);
    const int hi = lbound(bidx, NN, b + 1);
    const int t = threadIdx.x;
    if (t < 100) {
        float s = 0.f;
        for (int n = lo; n < hi; n++) s += g_nodeout[(size_t)n * 100 + t];
        out[b * 100 + t] = s;
    }
}

// =====================================================================
extern "C" void kernel_launch(void* const* d_in, const int* in_sizes, int n_in,
                              void* d_out, int out_size)
{
    const float* X    = (const float*)d_in[0];   // walk_feats (8192,10)
    const float* hop1 = (const float*)d_in[1];
    const float* hop2 = (const float*)d_in[2];
    const float* hop3 = (const float*)d_in[3];
    const int*   bidx = (const int*)d_in[4];
    const float* W1   = (const float*)d_in[5];   // (4,10,100)
    const float* b1   = (const float*)d_in[6];   // (4,100)
    const float* W2   = (const float*)d_in[7];   // (4,100,100)
    const float* b2   = (const float*)d_in[8];   // (4,100)
    float* out = (float*)d_out;                  // (256,100)

    (void)in_sizes; (void)n_in; (void)out_size;

    cudaFuncSetAttribute(hop_gemv_kernel, cudaFuncAttributeMaxDynamicSharedMemorySize, SMEM_A_BYTES);
    cudaFuncSetAttribute(mlp_kernel,      cudaFuncAttributeMaxDynamicSharedMemorySize, SMEM_B_BYTES);

    hop_gemv_kernel<<<768, 256, SMEM_A_BYTES>>>(hop1, hop2, hop3, X);
    mlp_kernel<<<256, 256, SMEM_B_BYTES>>>(X, W1, b1, W2, b2);
    segpool_kernel<<<NB_SEG, 128>>>(bidx, out);
}

// round 4
// speedup vs baseline: 1.5097x; 1.5097x over previous
#include <cuda_runtime.h>
#include <cstdint>
#include <cstddef>

#define NN 8192
#define RWD 10
#define HD1 100
#define HD2 100
#define NB_SEG 256

#define MSPLIT 8
#define MW 128                      // m-window per stage
#define ROWSB 128                   // rows per block (32 lanes x R=4)
#define ITERS ((NN / MSPLIT) / MW)  // 8
#define HOP_TILE_BYTES (ROWSB * MW * 4)   // 65536
#define X_TILE_BYTES (MW * RWD * 4)       // 5120
#define SMEM_A_BYTES (3 * (HOP_TILE_BYTES + X_TILE_BYTES))  // 211968

typedef unsigned long long u64;

// ---------------- scratch (static device arrays; no allocation) ----------------
__device__ float g_part[3 * MSPLIT * NN * RWD];  // per-m-split partials of hopX
__device__ float g_nodeout[NN * HD2];            // per-node summed MLP output

// ---------------- helpers ----------------
__device__ __forceinline__ void fma2(u64 &acc, u64 a, u64 b) {
    asm("fma.rn.f32x2 %0, %1, %2, %0;" : "+l"(acc) : "l"(a), "l"(b));
}
__device__ __forceinline__ u64 pack2(float x, float y) {
    u64 r; asm("mov.b64 %0, {%1, %2};" : "=l"(r) : "f"(x), "f"(y)); return r;
}
__device__ __forceinline__ float2 unpack2(u64 v) {
    float2 r; asm("mov.b64 {%0, %1}, %2;" : "=f"(r.x), "=f"(r.y) : "l"(v)); return r;
}
__device__ __forceinline__ void cp_async16(uint32_t dst, const void* src) {
    asm volatile("cp.async.cg.shared.global [%0], [%1], 16;" :: "r"(dst), "l"(src));
}
__device__ __forceinline__ void cp_commit() { asm volatile("cp.async.commit_group;"); }
template<int N> __device__ __forceinline__ void cp_wait() {
    asm volatile("cp.async.wait_group %0;" :: "n"(N));
}

// =====================================================================
// Kernel A: partial hopX over this block's m-range.
// Block: 256 thr / 8 warps, 128 rows, m-range = 1024 (one of 8 splits).
// Warp w owns m-subslice [w*16, w*16+16) of each 128-m window.
// Lane l accumulates 4 rows {l, l+32, l+64, l+96} -> X LDS amortized 4x.
// Hop tiles triple-buffered via cp.async; XOR-swizzled float4 layout.
// =====================================================================
extern "C" __global__ void __launch_bounds__(256, 1)
hop_gemv_kernel(const float* __restrict__ hop0, const float* __restrict__ hop1,
                const float* __restrict__ hop2, const float* __restrict__ X)
{
    extern __shared__ char smem[];
    float4* hsb[3] = { (float4*)smem,
                       (float4*)(smem + HOP_TILE_BYTES),
                       (float4*)(smem + 2 * HOP_TILE_BYTES) };
    float*  xsb[3] = { (float*)(smem + 3 * HOP_TILE_BYTES),
                       (float*)(smem + 3 * HOP_TILE_BYTES + X_TILE_BYTES),
                       (float*)(smem + 3 * HOP_TILE_BYTES + 2 * X_TILE_BYTES) };

    const int b   = blockIdx.x;                  // 1536 blocks
    const int k   = b >> 9;                      // 0..2
    const int rem = b & 511;
    const int rg  = rem >> 3;                    // row group 0..63
    const int sp  = rem & 7;                     // m split 0..7
    const int row0   = rg * ROWSB;
    const int m_base = sp * (NN / MSPLIT);
    const float* hop = (k == 0) ? hop0 : (k == 1) ? hop1 : hop2;

    const int t = threadIdx.x;
    const int w = t >> 5, l = t & 31;

    auto stage = [&](int buf, int it) {
        const int m0 = m_base + it * MW;
        const float* src = hop + (size_t)row0 * NN + m0;
        #pragma unroll
        for (int i = 0; i < 16; i++) {
            int f = i * 256 + t;
            int row = f >> 5, c4 = f & 31;
            uint32_t dst = (uint32_t)__cvta_generic_to_shared(
                &hsb[buf][row * 32 + (c4 ^ (row & 7))]);
            cp_async16(dst, src + (size_t)row * NN + c4 * 4);
        }
        // X chunk: 128 m x 10 floats = 5120B contiguous = 320 float4
        const float4* xsrc = (const float4*)(X + (size_t)m0 * RWD);
        uint32_t xdst = (uint32_t)__cvta_generic_to_shared(xsb[buf]);
        cp_async16(xdst + t * 16, xsrc + t);
        if (t < 64) cp_async16(xdst + (256 + t) * 16, xsrc + 256 + t);
        cp_commit();
    };

    u64 acc[4][5];
    #pragma unroll
    for (int g = 0; g < 4; g++)
        #pragma unroll
        for (int p = 0; p < 5; p++) acc[g][p] = 0ull;

    stage(0, 0);
    stage(1, 1);

    #pragma unroll 1
    for (int it = 0; it < ITERS; it++) {
        __syncthreads();                    // compute(it-1) done -> buffer (it+2)%3 free
        if (it + 2 < ITERS) { stage((it + 2) % 3, it + 2); cp_wait<2>(); }
        else if (it + 1 < ITERS) cp_wait<1>();
        else                     cp_wait<0>();
        __syncthreads();                    // buffer it visible to all warps

        const float4* hb = hsb[it % 3];
        const u64*    xb = (const u64*)xsb[it % 3];

        #pragma unroll
        for (int q = 0; q < 4; q++) {
            const int c4   = (w << 2) + q;
            const int slot = c4 ^ (l & 7);
            float4 h4[4];
            #pragma unroll
            for (int g = 0; g < 4; g++)
                h4[g] = hb[((l + (g << 5)) << 5) + slot];
            const u64* xp = xb + c4 * 20;   // 4 m's x 5 u64 (d-pairs)
            #pragma unroll
            for (int j = 0; j < 4; j++) {
                const float* hv0 = (const float*)&h4[0];
                const float* hv1 = (const float*)&h4[1];
                const float* hv2 = (const float*)&h4[2];
                const float* hv3 = (const float*)&h4[3];
                u64 A0 = pack2(hv0[j], hv0[j]);
                u64 A1 = pack2(hv1[j], hv1[j]);
                u64 A2 = pack2(hv2[j], hv2[j]);
                u64 A3 = pack2(hv3[j], hv3[j]);
                #pragma unroll
                for (int p = 0; p < 5; p++) {
                    u64 xv = xp[j * 5 + p];
                    fma2(acc[0][p], A0, xv);
                    fma2(acc[1][p], A1, xv);
                    fma2(acc[2][p], A2, xv);
                    fma2(acc[3][p], A3, xv);
                }
            }
        }
    }

    // cross-warp reduction (warps covered disjoint m-subslices)
    float* red = (float*)smem;              // alias hop buffer 0 (free now)
    __syncthreads();
    #pragma unroll
    for (int g = 0; g < 4; g++) {
        int row = l + (g << 5);
        #pragma unroll
        for (int p = 0; p < 5; p++) {
            float2 v = unpack2(acc[g][p]);
            red[(w * ROWSB + row) * RWD + 2 * p]     = v.x;
            red[(w * ROWSB + row) * RWD + 2 * p + 1] = v.y;
        }
    }
    __syncthreads();
    for (int f = t; f < ROWSB * RWD; f += 256) {
        int row = f / RWD, d = f % RWD;
        float s = 0.f;
        #pragma unroll
        for (int ww = 0; ww < 8; ww++) s += red[(ww * ROWSB + row) * RWD + d];
        g_part[((size_t)(k * MSPLIT + sp) * NN + row0 + row) * RWD + d] = s;
    }
}

// =====================================================================
// Kernel B: per node n: sum_k [ relu(inp_k . W1_k + b1_k) . W2_k ] + sum_k b2_k
// Input for k>=1 is the sum of the 8 m-split partials (deterministic order).
// =====================================================================
#define SMEM_B_BYTES ((112*100 + 32*100 + 100*12 + 320 + 100 + 100) * 4)

extern "C" __global__ void __launch_bounds__(256)
mlp_kernel(const float* __restrict__ X, const float* __restrict__ W1,
           const float* __restrict__ b1, const float* __restrict__ W2,
           const float* __restrict__ b2)
{
    extern __shared__ char smemb[];
    float* w2t = (float*)smemb;             // [112][100]  (rows 100..111 zero)
    float* hsm = w2t + 112 * 100;           // [32][100]
    float* w1t = hsm + 32 * 100;            // [100][12]
    float* inp = w1t + 100 * 12;            // [320]
    float* b1s = inp + 320;                 // [100]
    float* b2s = b1s + 100;                 // [100]

    const int t = threadIdx.x;
    const int node0 = blockIdx.x * 32;

    if (t < 100) b2s[t] = b2[t] + b2[100 + t] + b2[200 + t] + b2[300 + t];
    for (int f = t; f < 12 * 100; f += 256) w2t[100 * 100 + f] = 0.0f;

    const int r0 = t & 15;            // node row base
    const int ob = (t >> 4) * 7;      // output base (16 tiles x 7 = 112)
    u64 acc[2][7];
    #pragma unroll
    for (int g = 0; g < 2; g++)
        #pragma unroll
        for (int o = 0; o < 7; o++) acc[g][o] = 0ull;

    for (int k = 0; k < 4; k++) {
        __syncthreads();
        for (int f = t; f < 10000; f += 256) {
            int d = f / 100, o = f % 100;
            w2t[o * 100 + d] = W2[k * 10000 + f];     // transpose: [o][d]
        }
        for (int f = t; f < 1000; f += 256) {
            int r = f / 100, j = f % 100;
            w1t[j * 12 + r] = W1[k * 1000 + f];       // transpose: [j][r]
        }
        if (t < 100) b1s[t] = b1[k * 100 + t];
        if (k == 0) {
            const float* src = X + (size_t)node0 * RWD;
            for (int f = t; f < 320; f += 256) inp[f] = src[f];
        } else {
            const float* base = g_part + ((size_t)(k - 1) * MSPLIT * NN + node0) * RWD;
            for (int f = t; f < 320; f += 256) {
                float s = 0.f;
                #pragma unroll
                for (int sp = 0; sp < MSPLIT; sp++)
                    s += base[(size_t)sp * NN * RWD + f];
                inp[f] = s;
            }
        }
        __syncthreads();

        // phase 1: hsm[i][j] = relu(b1 + inp[i].W1[:,j])
        {
            const int i = t >> 3, jq = t & 7;
            float xr[10];
            #pragma unroll
            for (int r = 0; r < 10; r++) xr[r] = inp[i * 10 + r];
            #pragma unroll
            for (int jj = 0; jj < 13; jj++) {
                int j = jq * 13 + jj;
                if (j < 100) {
                    float s = b1s[j];
                    #pragma unroll
                    for (int r = 0; r < 10; r++) s = fmaf(xr[r], w1t[j * 12 + r], s);
                    hsm[i * 100 + j] = fmaxf(s, 0.0f);
                }
            }
        }
        __syncthreads();

        // phase 2: acc[g][oo] += hsm[row].w2t[o] over d (f32x2 pairs)
        #pragma unroll 5
        for (int d4 = 0; d4 < 25; d4++) {
            ulonglong2 h[2];
            #pragma unroll
            for (int g = 0; g < 2; g++)
                h[g] = *(const ulonglong2*)&hsm[(r0 + 16 * g) * 100 + d4 * 4];
            #pragma unroll
            for (int oo = 0; oo < 7; oo++) {
                ulonglong2 wv = *(const ulonglong2*)&w2t[(ob + oo) * 100 + d4 * 4];
                #pragma unroll
                for (int g = 0; g < 2; g++) {
                    fma2(acc[g][oo], h[g].x, wv.x);
                    fma2(acc[g][oo], h[g].y, wv.y);
                }
            }
        }
    }

    #pragma unroll
    for (int g = 0; g < 2; g++) {
        int n = node0 + r0 + 16 * g;
        #pragma unroll
        for (int oo = 0; oo < 7; oo++) {
            int o = ob + oo;
            if (o < 100) {
                float2 v = unpack2(acc[g][oo]);
                g_nodeout[(size_t)n * 100 + o] = v.x + v.y + b2s[o];
            }
        }
    }
}

// =====================================================================
// Kernel C: deterministic segment sum via binary search on sorted batch_idx
// =====================================================================
__device__ __forceinline__ int lbound(const int* a, int n, int v) {
    int lo = 0, hi = n;
    while (lo < hi) { int mid = (lo + hi) >> 1; if (a[mid] < v) lo = mid + 1; else hi = mid; }
    return lo;
}

extern "C" __global__ void segpool_kernel(const int* __restrict__ bidx,
                                          float* __restrict__ out)
{
    const int b = blockIdx.x;
    const int lo = lbound(bidx, NN, b);
    const int hi = lbound(bidx, NN, b + 1);
    const int t = threadIdx.x;
    if (t < 100) {
        float s = 0.f;
        for (int n = lo; n < hi; n++) s += g_nodeout[(size_t)n * 100 + t];
        out[b * 100 + t] = s;
    }
}

// =====================================================================
extern "C" void kernel_launch(void* const* d_in, const int* in_sizes, int n_in,
                              void* d_out, int out_size)
{
    const float* X    = (const float*)d_in[0];   // walk_feats (8192,10)
    const float* hop1 = (const float*)d_in[1];
    const float* hop2 = (const float*)d_in[2];
    const float* hop3 = (const float*)d_in[3];
    const int*   bidx = (const int*)d_in[4];
    const float* W1   = (const float*)d_in[5];   // (4,10,100)
    const float* b1   = (const float*)d_in[6];   // (4,100)
    const float* W2   = (const float*)d_in[7];   // (4,100,100)
    const float* b2   = (const float*)d_in[8];   // (4,100)
    float* out = (float*)d_out;                  // (256,100)

    (void)in_sizes; (void)n_in; (void)out_size;

    cudaFuncSetAttribute(hop_gemv_kernel, cudaFuncAttributeMaxDynamicSharedMemorySize, SMEM_A_BYTES);
    cudaFuncSetAttribute(mlp_kernel,      cudaFuncAttributeMaxDynamicSharedMemorySize, SMEM_B_BYTES);

    hop_gemv_kernel<<<1536, 256, SMEM_A_BYTES>>>(hop1, hop2, hop3, X);
    mlp_kernel<<<256, 256, SMEM_B_BYTES>>>(X, W1, b1, W2, b2);
    segpool_kernel<<<NB_SEG, 128>>>(bidx, out);
}

// round 6
// speedup vs baseline: 1.9012x; 1.2593x over previous
#include <cuda_runtime.h>
#include <cstdint>
#include <cstddef>

#define NN 8192
#define RWD 10
#define HD1 100
#define HD2 100
#define NB_SEG 256

#define MSPLIT 8
#define MW 64                       // m-window per stage
#define ROWSB 128                   // rows per block (32 lanes x 4)
#define ITERS ((NN / MSPLIT) / MW)  // 16
#define HOP_TILE_BYTES (ROWSB * MW * 4)   // 32768
#define X_TILE_BYTES (MW * RWD * 4)       // 2560
#define SMEM_A_BYTES (3 * (HOP_TILE_BYTES + X_TILE_BYTES))  // 105984 -> 2 blocks/SM

typedef unsigned long long u64;

// ---------------- scratch (static device arrays; no allocation) ----------------
__device__ float g_part[3 * MSPLIT * NN * RWD];  // per-m-split partials of hopX
__device__ float g_nodeout[NN * HD2];            // per-node summed MLP output

// ---------------- helpers ----------------
__device__ __forceinline__ void fma2(u64 &acc, u64 a, u64 b) {
    asm("fma.rn.f32x2 %0, %1, %2, %0;" : "+l"(acc) : "l"(a), "l"(b));
}
__device__ __forceinline__ u64 pack2(float x, float y) {
    u64 r; asm("mov.b64 %0, {%1, %2};" : "=l"(r) : "f"(x), "f"(y)); return r;
}
__device__ __forceinline__ float2 unpack2(u64 v) {
    float2 r; asm("mov.b64 {%0, %1}, %2;" : "=f"(r.x), "=f"(r.y) : "l"(v)); return r;
}
__device__ __forceinline__ void cp_async16(uint32_t dst, const void* src) {
    asm volatile("cp.async.cg.shared.global [%0], [%1], 16;" :: "r"(dst), "l"(src));
}
__device__ __forceinline__ void cp_commit() { asm volatile("cp.async.commit_group;"); }
template<int N> __device__ __forceinline__ void cp_wait() {
    asm volatile("cp.async.wait_group %0;" :: "n"(N));
}

// =====================================================================
// Kernel A: partial hopX over this block's m-range (1024 m of one hop).
// 256 thr / 8 warps, 128 rows. Warp w owns m-columns c4 in {2w, 2w+1}
// of each 64-m window; lane l accumulates rows {l, l+32, l+64, l+96}.
// Triple-buffered cp.async, 2 blocks resident per SM for stall overlap.
// =====================================================================
extern "C" __global__ void __launch_bounds__(256, 2)
hop_gemv_kernel(const float* __restrict__ hop0, const float* __restrict__ hop1,
                const float* __restrict__ hop2, const float* __restrict__ X)
{
    extern __shared__ char smem[];
    char* hop_s = smem;                                   // 3 x 32KB
    char* x_s   = smem + 3 * HOP_TILE_BYTES;              // 3 x 2.5KB

    const int b   = blockIdx.x;                  // 1536 blocks
    const int k   = b >> 9;                      // 0..2
    const int rem = b & 511;
    const int rg  = rem >> 3;                    // row group 0..63
    const int sp  = rem & 7;                     // m split 0..7
    const int row0   = rg * ROWSB;
    const int m_base = sp * (NN / MSPLIT);
    const float* hop = (k == 0) ? hop0 : (k == 1) ? hop1 : hop2;

    const int t = threadIdx.x;
    const int w = t >> 5, l = t & 31;

    // per-thread cp.async bases (stage deltas become immediates)
    const int tr = t >> 4;                    // 0..15 (row-within-16)
    const int tc = t & 15;                    // float4 column 0..15
    const int slotS = tc ^ (tr & 7);          // store slot: constant per thread
    const char* gsrc0 = (const char*)(hop + (size_t)(row0 + tr) * NN + m_base + tc * 4);
    const uint32_t hdst0 = (uint32_t)__cvta_generic_to_shared(hop_s)
                         + (uint32_t)((tr * 16 + slotS) * 16);
    const char* xsrc0 = (const char*)(X + (size_t)m_base * RWD);
    const uint32_t xdst0 = (uint32_t)__cvta_generic_to_shared(x_s) + (uint32_t)(t * 16);

    auto stage = [&](int buf, int it) {
        const char* gs = gsrc0 + (size_t)it * (MW * 4);
        uint32_t hd = hdst0 + buf * HOP_TILE_BYTES;
        #pragma unroll
        for (int i = 0; i < 8; i++)
            cp_async16(hd + i * 4096, gs + (size_t)i * (16 * NN * 4));
        if (t < 160)
            cp_async16(xdst0 + buf * X_TILE_BYTES, xsrc0 + (size_t)it * X_TILE_BYTES + t * 16);
        cp_commit();
    };

    u64 acc[4][5];
    #pragma unroll
    for (int g = 0; g < 4; g++)
        #pragma unroll
        for (int p = 0; p < 5; p++) acc[g][p] = 0ull;

    stage(0, 0);
    stage(1, 1);

    int bc = 2;                                  // buffer cursor for stage(it+2)
    #pragma unroll 1
    for (int it = 0; it < ITERS; it++) {
        __syncthreads();                    // compute(it-1) done -> buffer free
        if (it + 2 < ITERS) {
            stage(bc, it + 2);
            bc = (bc == 2) ? 0 : bc + 1;
            cp_wait<2>();
        } else if (it + 1 < ITERS) cp_wait<1>();
        else                       cp_wait<0>();
        __syncthreads();                    // buffer it visible to all warps

        const int cb = (it == 0) ? 0 : ((it % 3));
        const float4* hb = (const float4*)(hop_s + (it % 3) * HOP_TILE_BYTES);
        const u64*    xb = (const u64*)(x_s + (it % 3) * X_TILE_BYTES);
        (void)cb;

        #pragma unroll
        for (int q = 0; q < 2; q++) {
            const int c4   = (w << 1) + q;          // 0..15
            const int slot = c4 ^ (l & 7);
            float4 h4[4];
            #pragma unroll
            for (int g = 0; g < 4; g++)
                h4[g] = hb[((l + (g << 5)) << 4) + slot];
            const u64* xp = xb + c4 * 20;           // 4 m's x 5 u64 (d-pairs)
            #pragma unroll
            for (int j = 0; j < 4; j++) {
                const float* hv0 = (const float*)&h4[0];
                const float* hv1 = (const float*)&h4[1];
                const float* hv2 = (const float*)&h4[2];
                const float* hv3 = (const float*)&h4[3];
                u64 A0 = pack2(hv0[j], hv0[j]);
                u64 A1 = pack2(hv1[j], hv1[j]);
                u64 A2 = pack2(hv2[j], hv2[j]);
                u64 A3 = pack2(hv3[j], hv3[j]);
                #pragma unroll
                for (int p = 0; p < 5; p++) {
                    u64 xv = xp[j * 5 + p];
                    fma2(acc[0][p], A0, xv);
                    fma2(acc[1][p], A1, xv);
                    fma2(acc[2][p], A2, xv);
                    fma2(acc[3][p], A3, xv);
                }
            }
        }
    }

    // cross-warp reduction (warps covered disjoint m-subslices)
    float* red = (float*)smem;              // alias buffers (free now): 40KB needed
    __syncthreads();
    #pragma unroll
    for (int g = 0; g < 4; g++) {
        int row = l + (g << 5);
        #pragma unroll
        for (int p = 0; p < 5; p++) {
            float2 v = unpack2(acc[g][p]);
            red[(w * ROWSB + row) * RWD + 2 * p]     = v.x;
            red[(w * ROWSB + row) * RWD + 2 * p + 1] = v.y;
        }
    }
    __syncthreads();
    for (int f = t; f < ROWSB * RWD; f += 256) {
        int row = f / RWD, d = f % RWD;
        float s = 0.f;
        #pragma unroll
        for (int ww = 0; ww < 8; ww++) s += red[(ww * ROWSB + row) * RWD + d];
        g_part[((size_t)(k * MSPLIT + sp) * NN + row0 + row) * RWD + d] = s;
    }
}

// =====================================================================
// Kernel B: per node n: sum_k [ relu(inp_k . W1_k + b1_k) . W2_k ] + sum_k b2_k
// Input for k>=1 is the sum of the 8 m-split partials (deterministic order).
// =====================================================================
#define SMEM_B_BYTES ((112*100 + 32*100 + 100*12 + 320 + 100 + 100) * 4)

extern "C" __global__ void __launch_bounds__(256)
mlp_kernel(const float* __restrict__ X, const float* __restrict__ W1,
           const float* __restrict__ b1, const float* __restrict__ W2,
           const float* __restrict__ b2)
{
    extern __shared__ char smemb[];
    float* w2t = (float*)smemb;             // [112][100]  (rows 100..111 zero)
    float* hsm = w2t + 112 * 100;           // [32][100]
    float* w1t = hsm + 32 * 100;            // [100][12]
    float* inp = w1t + 100 * 12;            // [320]
    float* b1s = inp + 320;                 // [100]
    float* b2s = b1s + 100;                 // [100]

    const int t = threadIdx.x;
    const int node0 = blockIdx.x * 32;

    if (t < 100) b2s[t] = b2[t] + b2[100 + t] + b2[200 + t] + b2[300 + t];
    for (int f = t; f < 12 * 100; f += 256) w2t[100 * 100 + f] = 0.0f;

    const int r0 = t & 15;            // node row base
    const int ob = (t >> 4) * 7;      // output base (16 tiles x 7 = 112)
    u64 acc[2][7];
    #pragma unroll
    for (int g = 0; g < 2; g++)
        #pragma unroll
        for (int o = 0; o < 7; o++) acc[g][o] = 0ull;

    for (int k = 0; k < 4; k++) {
        __syncthreads();
        for (int f = t; f < 10000; f += 256) {
            int d = f / 100, o = f % 100;
            w2t[o * 100 + d] = W2[k * 10000 + f];     // transpose: [o][d]
        }
        for (int f = t; f < 1000; f += 256) {
            int r = f / 100, j = f % 100;
            w1t[j * 12 + r] = W1[k * 1000 + f];       // transpose: [j][r]
        }
        if (t < 100) b1s[t] = b1[k * 100 + t];
        if (k == 0) {
            const float* src = X + (size_t)node0 * RWD;
            for (int f = t; f < 320; f += 256) inp[f] = src[f];
        } else {
            const float* base = g_part + ((size_t)(k - 1) * MSPLIT * NN + node0) * RWD;
            for (int f = t; f < 320; f += 256) {
                float s = 0.f;
                #pragma unroll
                for (int sp = 0; sp < MSPLIT; sp++)
                    s += base[(size_t)sp * NN * RWD + f];
                inp[f] = s;
            }
        }
        __syncthreads();

        // phase 1: hsm[i][j] = relu(b1 + inp[i].W1[:,j])
        {
            const int i = t >> 3, jq = t & 7;
            float xr[10];
            #pragma unroll
            for (int r = 0; r < 10; r++) xr[r] = inp[i * 10 + r];
            #pragma unroll
            for (int jj = 0; jj < 13; jj++) {
                int j = jq * 13 + jj;
                if (j < 100) {
                    float s = b1s[j];
                    #pragma unroll
                    for (int r = 0; r < 10; r++) s = fmaf(xr[r], w1t[j * 12 + r], s);
                    hsm[i * 100 + j] = fmaxf(s, 0.0f);
                }
            }
        }
        __syncthreads();

        // phase 2: acc[g][oo] += hsm[row].w2t[o] over d (f32x2 pairs)
        #pragma unroll 5
        for (int d4 = 0; d4 < 25; d4++) {
            ulonglong2 h[2];
            #pragma unroll
            for (int g = 0; g < 2; g++)
                h[g] = *(const ulonglong2*)&hsm[(r0 + 16 * g) * 100 + d4 * 4];
            #pragma unroll
            for (int oo = 0; oo < 7; oo++) {
                ulonglong2 wv = *(const ulonglong2*)&w2t[(ob + oo) * 100 + d4 * 4];
                #pragma unroll
                for (int g = 0; g < 2; g++) {
                    fma2(acc[g][oo], h[g].x, wv.x);
                    fma2(acc[g][oo], h[g].y, wv.y);
                }
            }
        }
    }

    #pragma unroll
    for (int g = 0; g < 2; g++) {
        int n = node0 + r0 + 16 * g;
        #pragma unroll
        for (int oo = 0; oo < 7; oo++) {
            int o = ob + oo;
            if (o < 100) {
                float2 v = unpack2(acc[g][oo]);
                g_nodeout[(size_t)n * 100 + o] = v.x + v.y + b2s[o];
            }
        }
    }
}

// =====================================================================
// Kernel C: deterministic segment sum via binary search on sorted batch_idx
// =====================================================================
__device__ __forceinline__ int lbound(const int* a, int n, int v) {
    int lo = 0, hi = n;
    while (lo < hi) { int mid = (lo + hi) >> 1; if (a[mid] < v) lo = mid + 1; else hi = mid; }
    return lo;
}

extern "C" __global__ void segpool_kernel(const int* __restrict__ bidx,
                                          float* __restrict__ out)
{
    const int b = blockIdx.x;
    const int lo = lbound(bidx, NN, b);
    const int hi = lbound(bidx, NN, b + 1);
    const int t = threadIdx.x;
    if (t < 100) {
        float s = 0.f;
        int n = lo;
        for (; n + 3 < hi; n += 4) {
            s += g_nodeout[(size_t)n * 100 + t];
            s += g_nodeout[(size_t)(n + 1) * 100 + t];
            s += g_nodeout[(size_t)(n + 2) * 100 + t];
            s += g_nodeout[(size_t)(n + 3) * 100 + t];
        }
        for (; n < hi; n++) s += g_nodeout[(size_t)n * 100 + t];
        out[b * 100 + t] = s;
    }
}

// =====================================================================
extern "C" void kernel_launch(void* const* d_in, const int* in_sizes, int n_in,
                              void* d_out, int out_size)
{
    const float* X    = (const float*)d_in[0];   // walk_feats (8192,10)
    const float* hop1 = (const float*)d_in[1];
    const float* hop2 = (const float*)d_in[2];
    const float* hop3 = (const float*)d_in[3];
    const int*   bidx = (const int*)d_in[4];
    const float* W1   = (const float*)d_in[5];   // (4,10,100)
    const float* b1   = (const float*)d_in[6];   // (4,100)
    const float* W2   = (const float*)d_in[7];   // (4,100,100)
    const float* b2   = (const float*)d_in[8];   // (4,100)
    float* out = (float*)d_out;                  // (256,100)

    (void)in_sizes; (void)n_in; (void)out_size;

    cudaFuncSetAttribute(hop_gemv_kernel, cudaFuncAttributeMaxDynamicSharedMemorySize, SMEM_A_BYTES);
    cudaFuncSetAttribute(mlp_kernel,      cudaFuncAttributeMaxDynamicSharedMemorySize, SMEM_B_BYTES);

    hop_gemv_kernel<<<1536, 256, SMEM_A_BYTES>>>(hop1, hop2, hop3, X);
    mlp_kernel<<<256, 256, SMEM_B_BYTES>>>(X, W1, b1, W2, b2);
    segpool_kernel<<<NB_SEG, 128>>>(bidx, out);
}